// round 17
// baseline (speedup 1.0000x reference)
#include <cuda_runtime.h>
#include <cuda_fp16.h>
#include <cstdint>

// QuantumLinear == x @ W_real^T + bias  (magnitude*cos(atan2(i,r)) == r identically;
// weight_imag is dead code).
//
// Round 17: fp16 m16n8k16 single pass, 5-stage pipeline, but block barriers
// replaced with per-stage mbarrier producer/consumer pairs:
//   full[s]  (count 256): cp.async.mbarrier.arrive.noinc per thread
//   empty[s] (count 8):   lane0-per-warp arrive right after the warp's LAST
//                         read of the stage (slice1 ldsm at top of iter s)
// Warps free-run with ~1 iter skew instead of 128x block-barrier lockstep.

#define M_DIM 8192
#define N_DIM 4096
#define K_DIM 4096

#define BM 128
#define BN 128
#define BK 32                       // fp16 elements per K-tile (64B rows)
#define STAGES 5
#define KTILES (K_DIM / BK)         // 128

// smem rows: 64B data + 16B pad = 80B stride -> conflict-free ldmatrix
#define ROW_STRIDE 80
#define TILE_BYTES (128 * ROW_STRIDE)          // 10240
#define STAGE_BYTES (2 * TILE_BYTES)           // 20480
#define OFF_FULL(s)  ((s) * 8)                 // 5 x 8B
#define OFF_EMPTY(s) (64 + (s) * 8)            // 5 x 8B
#define OFF_STAGE    1024
#define SMEM_TOTAL (OFF_STAGE + STAGES * STAGE_BYTES)   // 103424 (x2 CTA = 202KB)

// ---------------- scratch: fp16 copies ----------------
__device__ __half g_xh[(size_t)M_DIM * K_DIM];
__device__ __half g_wh[(size_t)N_DIM * K_DIM];

// ---------------- helpers ----------------
__device__ __forceinline__ uint32_t smem_u32(const void* p) {
    uint32_t a;
    asm("{ .reg .u64 t; cvta.to.shared.u64 t, %1; cvt.u32.u64 %0, t; }" : "=r"(a) : "l"(p));
    return a;
}

__device__ __forceinline__ void cp16(uint32_t dst, const void* src) {
    asm volatile("cp.async.cg.shared.global [%0], [%1], 16;" :: "r"(dst), "l"(src));
}

#define MBAR_INIT(addr, cnt) \
    asm volatile("mbarrier.init.shared.b64 [%0], %1;" \
                 :: "r"((uint32_t)(addr)), "r"((uint32_t)(cnt)) : "memory")

// thread's prior cp.asyncs arrive (count 1, no expect-increment) on completion
#define CP_ARRIVE(addr) \
    asm volatile("cp.async.mbarrier.arrive.noinc.shared::cta.b64 [%0];" \
                 :: "r"((uint32_t)(addr)) : "memory")

#define MBAR_ARRIVE(addr) \
    asm volatile("mbarrier.arrive.shared::cta.b64 _, [%0];" \
                 :: "r"((uint32_t)(addr)) : "memory")

#define MBAR_WAIT(addr, par) do {                                                   \
    uint32_t _m = (uint32_t)(addr), _p = (uint32_t)(par);                           \
    asm volatile(                                                                   \
        "{\n\t.reg .pred P1;\n\t"                                                   \
        "WL_%=:\n\t"                                                                \
        "mbarrier.try_wait.parity.acquire.cta.shared::cta.b64 P1, [%0], %1, 0x989680;\n\t" \
        "@P1 bra.uni WD_%=;\n\t"                                                    \
        "bra.uni WL_%=;\n\t"                                                        \
        "WD_%=:\n\t}"                                                               \
        :: "r"(_m), "r"(_p) : "memory");                                            \
} while (0)

__device__ __forceinline__ void ldsm4(uint32_t* r, uint32_t addr) {
    asm volatile("ldmatrix.sync.aligned.m8n8.x4.shared.b16 {%0,%1,%2,%3}, [%4];"
                 : "=r"(r[0]), "=r"(r[1]), "=r"(r[2]), "=r"(r[3]) : "r"(addr));
}

__device__ __forceinline__ void mma16816(float* d, const uint32_t* a,
                                         uint32_t b0, uint32_t b1) {
    asm volatile(
        "mma.sync.aligned.m16n8k16.row.col.f32.f16.f16.f32 "
        "{%0,%1,%2,%3}, {%4,%5,%6,%7}, {%8,%9}, {%0,%1,%2,%3};"
        : "+f"(d[0]), "+f"(d[1]), "+f"(d[2]), "+f"(d[3])
        : "r"(a[0]), "r"(a[1]), "r"(a[2]), "r"(a[3]), "r"(b0), "r"(b1));
}

// ---------------- prep: fused fp32 -> fp16 (rn), 16B stores ----------------
#define NX16 ((size_t)M_DIM * K_DIM / 8)
#define NW16 ((size_t)N_DIM * K_DIM / 8)

__global__ __launch_bounds__(256)
void to_fp16_fused(const float4* __restrict__ xs, uint4* __restrict__ xd,
                   const float4* __restrict__ ws, uint4* __restrict__ wd)
{
    size_t i = (size_t)blockIdx.x * blockDim.x + threadIdx.x;
    const float4* s;
    uint4* d;
    if (i < NX16) { s = xs + 2 * i;            d = xd + i; }
    else          { size_t j = i - NX16; s = ws + 2 * j; d = wd + j; }
    float4 v0 = s[0];
    float4 v1 = s[1];
    __half2 h0 = __floats2half2_rn(v0.x, v0.y);
    __half2 h1 = __floats2half2_rn(v0.z, v0.w);
    __half2 h2 = __floats2half2_rn(v1.x, v1.y);
    __half2 h3 = __floats2half2_rn(v1.z, v1.w);
    uint4 o;
    o.x = *(uint32_t*)&h0;  o.y = *(uint32_t*)&h1;
    o.z = *(uint32_t*)&h2;  o.w = *(uint32_t*)&h3;
    *d = o;
}

// ---------------- GEMM ----------------
__global__ __launch_bounds__(256, 2)
void qgemm_fp16(const __half* __restrict__ X,   // [M, K] fp16
                const __half* __restrict__ W,   // [N, K] fp16
                const float* __restrict__ bias, // [N]
                float* __restrict__ out)        // [M, N]
{
    extern __shared__ char smem[];
    const uint32_t sb = smem_u32(smem);

    const int tid  = threadIdx.x;
    const int wid  = tid >> 5;
    const int lane = tid & 31;
    const int warpM = wid & 3;      // m offset 32*warpM
    const int warpN = wid >> 2;     // n offset 64*warpN

    // ---- grouped rasterization: 8 m-tiles per group column ----
    const int pid = blockIdx.x;
    const int group_id = pid >> 8;
    const int pid_m = (group_id << 3) + (pid & 7);
    const int pid_n = (pid & 255) >> 3;
    const int bm = pid_m * BM;
    const int bn = pid_n * BN;

    // ---- global load mapping: 2 rows per thread per tile, 16B chunks ----
    const int ldr   = tid >> 2;
    const int chunk = tid & 3;
    const size_t aOff0 = (size_t)(bm + ldr) * K_DIM + chunk * 8;
    const size_t aOff1 = aOff0 + (size_t)64 * K_DIM;
    const size_t bOff0 = (size_t)(bn + ldr) * K_DIM + chunk * 8;
    const size_t bOff1 = bOff0 + (size_t)64 * K_DIM;
    const uint32_t sA0 = ldr * ROW_STRIDE + chunk * 16;
    const uint32_t sA1 = sA0 + 64 * ROW_STRIDE;

    // ---- ldmatrix lane bases ----
    const uint32_t aLane = sb + OFF_STAGE +
        (uint32_t)((warpM * 32 + (lane & 15)) * ROW_STRIDE + ((lane >> 4) * 16));
    const uint32_t bLane = sb + OFF_STAGE + TILE_BYTES +
        (uint32_t)((warpN * 64 + (lane & 7) + ((lane & 16) >> 1)) * ROW_STRIDE +
                   (((lane >> 3) & 1) * 16));

    // ---- mbarrier init ----
    if (tid == 0) {
        #pragma unroll
        for (int s = 0; s < STAGES; s++) {
            MBAR_INIT(sb + OFF_FULL(s), 256);   // one cp-arrive per thread
            MBAR_INIT(sb + OFF_EMPTY(s), 8);    // one arrive per warp (lane 0)
        }
    }
    __syncthreads();   // barriers visible before any cp-arrive targets them

    float acc[2][8][4];
    #pragma unroll
    for (int i = 0; i < 2; i++)
        #pragma unroll
        for (int j = 0; j < 8; j++)
            #pragma unroll
            for (int q = 0; q < 4; q++)
                acc[i][j][q] = 0.0f;

    // ---- prologue: prime tiles 0..3 into stages 0..3 ----
    #pragma unroll
    for (int s = 0; s < 4; s++) {
        const int k0 = s * BK;
        const uint32_t st = sb + OFF_STAGE + s * STAGE_BYTES;
        cp16(st + sA0, X + aOff0 + k0);
        cp16(st + sA1, X + aOff1 + k0);
        cp16(st + TILE_BYTES + sA0, W + bOff0 + k0);
        cp16(st + TILE_BYTES + sA1, W + bOff1 + k0);
        CP_ARRIVE(sb + OFF_FULL(s));
    }

    // fragment slots
    uint32_t ar[2][2][4];   // [slice][mt][reg]
    uint32_t br[2][4][4];   // [slice][npair][reg]

    // ---- consume tile 0 slice0 ----
    MBAR_WAIT(sb + OFF_FULL(0), 0);
    {
        const uint32_t o = sb + OFF_STAGE - sb;  // stage 0 offset from lane bases
        ldsm4(ar[0][0], aLane);
        ldsm4(ar[0][1], aLane + 16 * ROW_STRIDE);
        #pragma unroll
        for (int p = 0; p < 4; p++)
            ldsm4(br[0][p], bLane + p * (16 * ROW_STRIDE));
        (void)o;
    }

    // cursors (all offsets relative to lane bases / stage area)
    uint32_t oC = 0;                         // stage of tile s
    int slotP = 4, phP = 1;                  // producer empty-wait: tile s+4
    int slotF = 1, phF = 0;                  // consumer full-wait: tile s+1

    // ---- main loop: no __syncthreads ----
    #pragma unroll 1
    for (int s = 0; s < KTILES; s++) {
        const int slotC = (slotF == 0) ? 4 : slotF - 1;   // s % 5

        // 1) last read of stage s: slice1 ldsm
        {
            const uint32_t o = oC + 32;
            ldsm4(ar[1][0], aLane + o);
            ldsm4(ar[1][1], aLane + o + 16 * ROW_STRIDE);
            #pragma unroll
            for (int p = 0; p < 4; p++)
                ldsm4(br[1][p], bLane + o + p * (16 * ROW_STRIDE));
        }
        // 2) this warp is done with stage s -> release it
        if (lane == 0) MBAR_ARRIVE(sb + OFF_EMPTY(slotC));

        // 3) mma slice0 (fragments preloaded last iteration)
        #pragma unroll
        for (int mt = 0; mt < 2; mt++)
            #pragma unroll
            for (int nt = 0; nt < 8; nt++)
                mma16816(acc[mt][nt], ar[0][mt],
                         br[0][nt >> 1][(nt & 1) * 2],
                         br[0][nt >> 1][(nt & 1) * 2 + 1]);

        // 4) producer: tile s+4 into stage (s+4)%5 == (s-1)%5
        const int ls = s + 4;
        if (ls < KTILES) {
            MBAR_WAIT(sb + OFF_EMPTY(slotP), phP);
            const int k0 = ls * BK;
            const uint32_t st = sb + OFF_STAGE + slotP * STAGE_BYTES;
            cp16(st + sA0, X + aOff0 + k0);
            cp16(st + sA1, X + aOff1 + k0);
            cp16(st + TILE_BYTES + sA0, W + bOff0 + k0);
            cp16(st + TILE_BYTES + sA1, W + bOff1 + k0);
            CP_ARRIVE(sb + OFF_FULL(slotP));
        }

        // 5) cross-iteration preload: tile s+1 slice0
        if (s + 1 < KTILES) {
            MBAR_WAIT(sb + OFF_FULL(slotF), phF);
            const uint32_t oN = (uint32_t)(slotF * STAGE_BYTES);
            ldsm4(ar[0][0], aLane + oN);
            ldsm4(ar[0][1], aLane + oN + 16 * ROW_STRIDE);
            #pragma unroll
            for (int p = 0; p < 4; p++)
                ldsm4(br[0][p], bLane + oN + p * (16 * ROW_STRIDE));
            oC = oN;
        }

        // 6) mma slice1
        #pragma unroll
        for (int mt = 0; mt < 2; mt++)
            #pragma unroll
            for (int nt = 0; nt < 8; nt++)
                mma16816(acc[mt][nt], ar[1][mt],
                         br[1][nt >> 1][(nt & 1) * 2],
                         br[1][nt >> 1][(nt & 1) * 2 + 1]);

        // advance cursors
        if (++slotP == STAGES) { slotP = 0; phP ^= 1; }
        if (++slotF == STAGES) { slotF = 0; phF ^= 1; }
    }

    // ---- epilogue: direct stores + bias ----
    const int g = lane >> 2;
    const int t = lane & 3;
    #pragma unroll
    for (int mt = 0; mt < 2; mt++) {
        const int row0 = bm + warpM * 32 + mt * 16 + g;
        #pragma unroll
        for (int nt = 0; nt < 8; nt++) {
            const int col = bn + warpN * 64 + nt * 8 + 2 * t;
            const float2 b2 = *(const float2*)(bias + col);
            float2 o0, o1;
            o0.x = acc[mt][nt][0] + b2.x;
            o0.y = acc[mt][nt][1] + b2.y;
            o1.x = acc[mt][nt][2] + b2.x;
            o1.y = acc[mt][nt][3] + b2.y;
            *(float2*)(out + (size_t)row0 * N_DIM + col)       = o0;
            *(float2*)(out + (size_t)(row0 + 8) * N_DIM + col) = o1;
        }
    }
}

// ---------------- host ----------------
extern "C" void kernel_launch(void* const* d_in, const int* in_sizes, int n_in,
                              void* d_out, int out_size)
{
    const float* x    = (const float*)d_in[0];   // [M, K]
    const float* wr   = (const float*)d_in[1];   // [N, K]
    // d_in[2] = weight_imag: algebraically dead
    const float* bias = (const float*)d_in[3];   // [N]
    float* out = (float*)d_out;

    void *p_xh, *p_wh;
    cudaGetSymbolAddress(&p_xh, g_xh);
    cudaGetSymbolAddress(&p_wh, g_wh);

    const int nblocks_prep = (int)((NX16 + NW16) / 256);
    to_fp16_fused<<<nblocks_prep, 256>>>(
        (const float4*)x, (uint4*)p_xh,
        (const float4*)wr, (uint4*)p_wh);

    cudaFuncSetAttribute(qgemm_fp16, cudaFuncAttributeMaxDynamicSharedMemorySize,
                         SMEM_TOTAL);

    const int nblocks = (M_DIM / BM) * (N_DIM / BN);   // 2048
    qgemm_fp16<<<nblocks, 256, SMEM_TOTAL>>>(
        (const __half*)p_xh, (const __half*)p_wh, bias, out);
}